// round 3
// baseline (speedup 1.0000x reference)
#include <cuda_runtime.h>
#include <cstdint>

// ---------------- problem constants ----------------
constexpr int NN   = 100000;   // nodes
constexpr int SS   = 2;        // layout samples
constexpr int GG   = 8;        // graphs
constexpr int EE   = 400000;   // edges
constexpr int MIDC = 256;      // mid channels
constexpr int NL   = 4;        // layers
constexpr int KIN  = 265;      // input channels
constexpr int KPAD = 272;      // padded to multiple of 16 (and 16B-aligned rows)
constexpr int MROWS = SS * NN; // 200000 GEMM rows

// ---------------- static scratch (device globals; no allocation) ----------------
__device__ float g_xin[(size_t)MROWS * KPAD];   // assembled input  [S*N, 272]
__device__ float g_xa [(size_t)MROWS * MIDC];   // ping
__device__ float g_xb [(size_t)MROWS * MIDC];   // pong
__device__ float g_af [(size_t)MROWS * MIDC];   // fwd aggregation (pre-scaled)
__device__ float g_ar [(size_t)MROWS * MIDC];   // rev aggregation (pre-scaled)
__device__ int   g_cntf[NN], g_cntr[NN];
__device__ int   g_offf[NN + 1], g_offr[NN + 1];
__device__ int   g_curf[NN], g_curr[NN];
__device__ int   g_csrf[EE], g_csrr[EE];
__device__ float g_invf[NN], g_invr[NN];

// ---------------- small helpers ----------------
typedef unsigned long long u64;

__device__ __forceinline__ void ffma2(u64& d, u64 a, u64 b) {
    asm("fma.rn.f32x2 %0, %1, %2, %0;" : "+l"(d) : "l"(a), "l"(b));
}
__device__ __forceinline__ u64 pk2(float lo, float hi) {
    u64 r; asm("mov.b64 %0, {%1, %2};" : "=l"(r) : "f"(lo), "f"(hi)); return r;
}
__device__ __forceinline__ u64 dup2(float x) {
    u64 r; asm("mov.b64 %0, {%1, %1};" : "=l"(r) : "f"(x)); return r;
}
__device__ __forceinline__ float2 un2(u64 v) {
    float2 r; asm("mov.b64 {%0, %1}, %2;" : "=f"(r.x), "=f"(r.y) : "l"(v)); return r;
}
__device__ __forceinline__ void add4(float4& a, float4 b) {
    a.x += b.x; a.y += b.y; a.z += b.z; a.w += b.w;
}
__device__ __forceinline__ float4 mul4(float4 a, float s) {
    return make_float4(a.x * s, a.y * s, a.z * s, a.w * s);
}

// ---------------- input assembly: [S*N, 272] with zero pad ----------------
__global__ void assemble_kernel(const float* __restrict__ xf,
                                const float* __restrict__ dimf,
                                const float* __restrict__ layf,
                                const float* __restrict__ tilef,
                                const float* __restrict__ emb,
                                const int*   __restrict__ opc,
                                const int*   __restrict__ batch) {
    long idx = (long)blockIdx.x * blockDim.x + threadIdx.x;
    long total = (long)MROWS * KPAD;
    if (idx >= total) return;
    int c = (int)(idx % KPAD);
    int rem = (int)(idx / KPAD);
    int n = rem % NN;
    int s = rem / NN;
    float v;
    if (c < 53)       v = xf[(size_t)n * 53 + c];
    else if (c < 85)  v = emb[(size_t)opc[n] * 32 + (c - 53)];
    else if (c < 223) v = dimf[(size_t)n * 138 + (c - 85)];
    else if (c < 247) v = layf[((size_t)n * SS + s) * 24 + (c - 223)];
    else if (c < KIN) v = tilef[((size_t)batch[n] * SS + s) * 18 + (c - 247)];
    else              v = 0.f;
    g_xin[idx] = v;
}

// ---------------- degree histogram ----------------
__global__ void hist_kernel(const int* __restrict__ src, const int* __restrict__ tgt) {
    int e = blockIdx.x * blockDim.x + threadIdx.x;
    if (e >= EE) return;
    atomicAdd(&g_cntf[tgt[e]], 1);
    atomicAdd(&g_cntr[src[e]], 1);
}

// ---------------- exclusive scan (one block per direction) ----------------
__global__ void scan_kernel() {
    const int* cnt = blockIdx.x ? g_cntr : g_cntf;
    int* off       = blockIdx.x ? g_offr : g_offf;
    __shared__ int wsum[32];
    __shared__ int chunk_total;
    __shared__ int carry;
    int tid = threadIdx.x, lane = tid & 31, wid = tid >> 5;
    if (tid == 0) carry = 0;
    __syncthreads();
    for (int base = 0; base < NN; base += 1024) {
        int i = base + tid;
        int v = (i < NN) ? cnt[i] : 0;
        int x = v;
        #pragma unroll
        for (int d = 1; d < 32; d <<= 1) {
            int t = __shfl_up_sync(0xffffffffu, x, d);
            if (lane >= d) x += t;
        }
        if (lane == 31) wsum[wid] = x;
        __syncthreads();
        if (wid == 0) {
            int wv = wsum[lane];
            int y = wv;
            #pragma unroll
            for (int d = 1; d < 32; d <<= 1) {
                int t = __shfl_up_sync(0xffffffffu, y, d);
                if (lane >= d) y += t;
            }
            if (lane == 31) chunk_total = y;
            wsum[lane] = y - wv;   // exclusive warp offset
        }
        __syncthreads();
        if (i < NN) off[i] = carry + wsum[wid] + (x - v);
        __syncthreads();
        if (tid == 0) carry += chunk_total;
        __syncthreads();
    }
    if (threadIdx.x == 0) off[NN] = carry;
}

// ---------------- inv-degree + cursor init ----------------
__global__ void invcur_kernel() {
    int i = blockIdx.x * blockDim.x + threadIdx.x;
    if (i >= NN) return;
    g_invf[i] = 1.f / fmaxf((float)g_cntf[i], 1.f);
    g_invr[i] = 1.f / fmaxf((float)g_cntr[i], 1.f);
    g_curf[i] = g_offf[i];
    g_curr[i] = g_offr[i];
}

// ---------------- CSR fill ----------------
__global__ void fill_kernel(const int* __restrict__ src, const int* __restrict__ tgt) {
    int e = blockIdx.x * blockDim.x + threadIdx.x;
    if (e >= EE) return;
    int s = src[e], t = tgt[e];
    g_csrf[atomicAdd(&g_curf[t], 1)] = s;   // fwd: in-neighbors of t
    g_csrr[atomicAdd(&g_curr[s], 1)] = t;   // rev: out-neighbors of s
}

// ---------------- neighbor-mean gather (both samples, dir = blockIdx.y) ----------------
__global__ void gather_kernel(const float* __restrict__ x) {
    int w = (blockIdx.x * blockDim.x + threadIdx.x) >> 5;
    int lane = threadIdx.x & 31;
    if (w >= NN) return;
    const int dir = blockIdx.y;
    const int*   off = dir ? g_offr : g_offf;
    const int*   csr = dir ? g_csrr : g_csrf;
    const float* inv = dir ? g_invr : g_invf;
    float*       agg = dir ? g_ar   : g_af;

    int b0 = off[w], b1 = off[w + 1];
    float4 a00 = make_float4(0, 0, 0, 0), a01 = a00, a10 = a00, a11 = a00;
    for (int j = b0; j < b1; j++) {
        int nb = csr[j];
        const float4* p0 = reinterpret_cast<const float4*>(x + (size_t)nb * MIDC) + lane * 2;
        const float4* p1 = reinterpret_cast<const float4*>(x + ((size_t)NN + nb) * MIDC) + lane * 2;
        add4(a00, p0[0]); add4(a01, p0[1]);
        add4(a10, p1[0]); add4(a11, p1[1]);
    }
    float iv = inv[w];
    float4* q0 = reinterpret_cast<float4*>(agg + (size_t)w * MIDC) + lane * 2;
    float4* q1 = reinterpret_cast<float4*>(agg + ((size_t)NN + w) * MIDC) + lane * 2;
    q0[0] = mul4(a00, iv); q0[1] = mul4(a01, iv);
    q1[0] = mul4(a10, iv); q1[1] = mul4(a11, iv);
}

// ---------------- fused dual GEMM:  C = relu(A1*W1 + A2*W2 + bias) ----------------
// A padded so K-tiles need no A-side k-guard; W guarded by kw.
constexpr int BM = 128, BN = 128, BK = 16;

__global__ __launch_bounds__(256, 2)
void gemm_dual(const float* __restrict__ A1, const float* __restrict__ W1,
               int kt1, int kw1, int lda1,
               const float* __restrict__ A2, const float* __restrict__ W2,
               int kt2, int kw2, int lda2,
               int ldw,
               const float* __restrict__ bias,
               float* __restrict__ C, int M, int ldc) {
    __shared__ float As[BK][BM + 4];
    __shared__ float Bs[BK][BN + 4];
    const int tid = threadIdx.x;
    const int tx = tid & 15, ty = tid >> 4;
    const int m0 = blockIdx.x * BM;
    const int n0 = blockIdx.y * BN;

    u64 acc[4][8];
    #pragma unroll
    for (int i = 0; i < 4; i++)
        #pragma unroll
        for (int j = 0; j < 8; j++) acc[i][j] = 0ull;

    for (int pass = 0; pass < 2; pass++) {
        const float* A = pass ? A2 : A1;
        if (!A) break;
        const float* W = pass ? W2 : W1;
        const int kt  = pass ? kt2  : kt1;
        const int kw  = pass ? kw2  : kw1;
        const int lda = pass ? lda2 : lda1;
        for (int t = 0; t < kt; t++) {
            const int k0 = t * BK;
            #pragma unroll
            for (int l = 0; l < 2; l++) {
                int j = tid + l * 256;
                int r  = j >> 2;
                int kq = (j & 3) << 2;
                int m = m0 + r;
                float4 f = make_float4(0.f, 0.f, 0.f, 0.f);
                if (m < M) f = *reinterpret_cast<const float4*>(A + (size_t)m * lda + (k0 + kq));
                As[kq + 0][r] = f.x; As[kq + 1][r] = f.y;
                As[kq + 2][r] = f.z; As[kq + 3][r] = f.w;
            }
            #pragma unroll
            for (int l = 0; l < 2; l++) {
                int j = tid + l * 256;
                int k  = j >> 5;
                int nq = (j & 31) << 2;
                float4 f = make_float4(0.f, 0.f, 0.f, 0.f);
                if (k0 + k < kw) f = *reinterpret_cast<const float4*>(W + (size_t)(k0 + k) * ldw + n0 + nq);
                *reinterpret_cast<float4*>(&Bs[k][nq]) = f;
            }
            __syncthreads();
            #pragma unroll
            for (int k = 0; k < BK; k++) {
                float4 a0 = *reinterpret_cast<const float4*>(&As[k][ty * 8]);
                float4 a1 = *reinterpret_cast<const float4*>(&As[k][ty * 8 + 4]);
                float4 b0 = *reinterpret_cast<const float4*>(&Bs[k][tx * 8]);
                float4 b1 = *reinterpret_cast<const float4*>(&Bs[k][tx * 8 + 4]);
                u64 ap[4];
                ap[0] = pk2(a0.x, a0.y); ap[1] = pk2(a0.z, a0.w);
                ap[2] = pk2(a1.x, a1.y); ap[3] = pk2(a1.z, a1.w);
                float bv[8] = {b0.x, b0.y, b0.z, b0.w, b1.x, b1.y, b1.z, b1.w};
                #pragma unroll
                for (int j = 0; j < 8; j++) {
                    u64 bd = dup2(bv[j]);
                    ffma2(acc[0][j], ap[0], bd);
                    ffma2(acc[1][j], ap[1], bd);
                    ffma2(acc[2][j], ap[2], bd);
                    ffma2(acc[3][j], ap[3], bd);
                }
            }
            __syncthreads();
        }
    }
    // epilogue: bias + relu, float4 stores
    float cv[8][8];
    #pragma unroll
    for (int i2 = 0; i2 < 4; i2++)
        #pragma unroll
        for (int j = 0; j < 8; j++) {
            float2 v = un2(acc[i2][j]);
            cv[2 * i2][j] = v.x; cv[2 * i2 + 1][j] = v.y;
        }
    #pragma unroll
    for (int i = 0; i < 8; i++) {
        int m = m0 + ty * 8 + i;
        if (m >= M) continue;
        #pragma unroll
        for (int jq = 0; jq < 2; jq++) {
            int n = n0 + tx * 8 + jq * 4;
            float4 o;
            o.x = fmaxf(cv[i][jq * 4 + 0] + bias[n + 0], 0.f);
            o.y = fmaxf(cv[i][jq * 4 + 1] + bias[n + 1], 0.f);
            o.z = fmaxf(cv[i][jq * 4 + 2] + bias[n + 2], 0.f);
            o.w = fmaxf(cv[i][jq * 4 + 3] + bias[n + 3], 0.f);
            *reinterpret_cast<float4*>(C + (size_t)m * ldc + n) = o;
        }
    }
}

// ---------------- head ----------------
__global__ void init_out_kernel(float* out, const float* __restrict__ hb) {
    int i = threadIdx.x;
    if (i < GG * SS) out[i] = hb[0];
}

__global__ void head_kernel(const float* __restrict__ x2,   // layer-2 output (headW[0:256])
                            const float* __restrict__ x3,   // layer-3 output (headW[256:512])
                            const float* __restrict__ hw,
                            const int*   __restrict__ batch,
                            float* __restrict__ out) {
    __shared__ float part[GG * SS];
    int tid = threadIdx.x;
    if (tid < GG * SS) part[tid] = 0.f;
    __syncthreads();
    int w = (blockIdx.x * blockDim.x + tid) >> 5;
    int lane = tid & 31;
    if (w < NN) {
        int g = batch[w];
        #pragma unroll
        for (int s = 0; s < SS; s++) {
            const float* p2 = x2 + ((size_t)s * NN + w) * MIDC;
            const float* p3 = x3 + ((size_t)s * NN + w) * MIDC;
            float sum = 0.f;
            #pragma unroll
            for (int c = lane; c < MIDC; c += 32)
                sum += p2[c] * hw[c] + p3[c] * hw[MIDC + c];
            #pragma unroll
            for (int d = 16; d > 0; d >>= 1) sum += __shfl_down_sync(0xffffffffu, sum, d);
            if (lane == 0) atomicAdd(&part[g * SS + s], sum);
        }
    }
    __syncthreads();
    if (tid < GG * SS && part[tid] != 0.f) atomicAdd(&out[tid], part[tid]);
}

// ---------------- launch ----------------
extern "C" void kernel_launch(void* const* d_in, const int* in_sizes, int n_in,
                              void* d_out, int out_size) {
    const float* x_feat    = (const float*)d_in[0];
    const float* dim_feat  = (const float*)d_in[1];
    const float* lay_feat  = (const float*)d_in[2];
    const float* tile_feat = (const float*)d_in[3];
    const float* emb       = (const float*)d_in[4];
    const float* preW      = (const float*)d_in[5];
    const float* preb      = (const float*)d_in[6];
    const float* convWl    = (const float*)d_in[7];
    const float* convWr    = (const float*)d_in[8];
    const float* convb     = (const float*)d_in[9];
    const float* revWl     = (const float*)d_in[10];
    const float* revWr     = (const float*)d_in[11];
    const float* revb      = (const float*)d_in[12];
    const float* headW     = (const float*)d_in[13];
    const float* headb     = (const float*)d_in[14];
    const int*   opcode    = (const int*)d_in[15];
    const int*   batch     = (const int*)d_in[16];
    const int*   eidx      = (const int*)d_in[17];
    const int* src = eidx;
    const int* tgt = eidx + EE;
    float* out = (float*)d_out;

    float *xin, *xa, *xb, *af, *ar;
    int *cntf, *cntr;
    cudaGetSymbolAddress((void**)&xin,  g_xin);
    cudaGetSymbolAddress((void**)&xa,   g_xa);
    cudaGetSymbolAddress((void**)&xb,   g_xb);
    cudaGetSymbolAddress((void**)&af,   g_af);
    cudaGetSymbolAddress((void**)&ar,   g_ar);
    cudaGetSymbolAddress((void**)&cntf, g_cntf);
    cudaGetSymbolAddress((void**)&cntr, g_cntr);

    // graph structure (recomputed every call; capturable)
    cudaMemsetAsync(cntf, 0, NN * sizeof(int), 0);
    cudaMemsetAsync(cntr, 0, NN * sizeof(int), 0);
    hist_kernel<<<(EE + 255) / 256, 256>>>(src, tgt);
    scan_kernel<<<2, 1024>>>();
    invcur_kernel<<<(NN + 255) / 256, 256>>>();
    fill_kernel<<<(EE + 255) / 256, 256>>>(src, tgt);

    // input assembly
    {
        long total = (long)MROWS * KPAD;
        assemble_kernel<<<(unsigned)((total + 255) / 256), 256>>>(
            x_feat, dim_feat, lay_feat, tile_feat, emb, opcode, batch);
    }

    // pre-GEMM: xa = relu(xin @ preW + preb)
    {
        dim3 grid((MROWS + BM - 1) / BM, MIDC / BN);
        gemm_dual<<<grid, 256>>>(xin, preW, KPAD / BK, KIN, KPAD,
                                 nullptr, nullptr, 0, 0, 0,
                                 MIDC, preb, xa, MROWS, MIDC);
    }

    float* cur = xa;
    float* nxt = xb;
    for (int i = 0; i < NL; i++) {
        dim3 gg((NN * 32 + 255) / 256, 2);
        gather_kernel<<<gg, 256>>>(cur);
        dim3 grid((MROWS + BM - 1) / BM, 1);
        gemm_dual<<<grid, 256>>>(af, convWl + (size_t)i * MIDC * 128, MIDC / BK, MIDC, MIDC,
                                 cur, convWr + (size_t)i * MIDC * 128, MIDC / BK, MIDC, MIDC,
                                 128, convb + i * 128, nxt, MROWS, MIDC);
        gemm_dual<<<grid, 256>>>(ar, revWl + (size_t)i * MIDC * 128, MIDC / BK, MIDC, MIDC,
                                 cur, revWr + (size_t)i * MIDC * 128, MIDC / BK, MIDC, MIDC,
                                 128, revb + i * 128, nxt + 128, MROWS, MIDC);
        float* tmp = cur; cur = nxt; nxt = tmp;
    }
    // After 4 layers: layer-2 output in g_xb, layer-3 output in g_xa.

    init_out_kernel<<<1, 32>>>(out, headb);
    head_kernel<<<(NN * 32 + 255) / 256, 256>>>(xb, xa, headW, batch, out);
}

// round 5
// speedup vs baseline: 1.8586x; 1.8586x over previous
#include <cuda_runtime.h>
#include <cuda_bf16.h>
#include <cstdint>

// ---------------- problem constants ----------------
constexpr int NN   = 100000;
constexpr int SAMP = 2;
constexpr int GG   = 8;
constexpr int EE   = 400000;
constexpr int MIDC = 256;
constexpr int NL   = 4;
constexpr int KIN  = 265;
constexpr int KPRE = 288;              // padded input K (9 chunks of 32)
constexpr int MROWS = SAMP * NN;       // 200000
constexpr int MPAD  = 200064;          // 1563 * 128
constexpr int MTILES = MPAD / 128;

// ---------------- static scratch ----------------
__device__ float g_xin[(size_t)MPAD * KPRE];
__device__ float g_xa [(size_t)MPAD * MIDC];
__device__ float g_xb [(size_t)MPAD * MIDC];
__device__ float g_P  [(size_t)MPAD * 512];
__device__ __nv_bfloat16 g_wpre[2 * 256 * KPRE];        // [plane][n256][k288]
__device__ __nv_bfloat16 g_wlay[NL * 2 * 512 * 256];    // [l][plane][n512][k256]
__device__ int   g_cntf[NN], g_cntr[NN];
__device__ int   g_offf[NN + 1], g_offr[NN + 1];
__device__ int   g_curf[NN], g_curr[NN];
__device__ int   g_csrf[EE], g_csrr[EE];
__device__ float g_invf[NN], g_invr[NN];

// ---------------- PTX helpers ----------------
__device__ __forceinline__ uint32_t smem_u32(const void* p) {
    uint32_t a;
    asm("{ .reg .u64 t; cvta.to.shared.u64 t, %1; cvt.u32.u64 %0, t; }" : "=r"(a) : "l"(p));
    return a;
}
__device__ __forceinline__ void cp16(uint32_t dst, const void* src) {
    asm volatile("cp.async.ca.shared.global [%0], [%1], 16;" :: "r"(dst), "l"(src));
}
__device__ __forceinline__ void cp_commit() { asm volatile("cp.async.commit_group;"); }
__device__ __forceinline__ void cp_wait0()  { asm volatile("cp.async.wait_group 0;"); }
__device__ __forceinline__ void ldsm4(uint32_t* r, uint32_t a) {
    asm volatile("ldmatrix.sync.aligned.m8n8.x4.shared.b16 {%0,%1,%2,%3}, [%4];"
                 : "=r"(r[0]), "=r"(r[1]), "=r"(r[2]), "=r"(r[3]) : "r"(a));
}
__device__ __forceinline__ void mma16816(float* d, const uint32_t* a, const uint32_t* b) {
    asm volatile("mma.sync.aligned.m16n8k16.row.col.f32.bf16.bf16.f32 "
                 "{%0,%1,%2,%3}, {%4,%5,%6,%7}, {%8,%9}, {%0,%1,%2,%3};"
                 : "+f"(d[0]), "+f"(d[1]), "+f"(d[2]), "+f"(d[3])
                 : "r"(a[0]), "r"(a[1]), "r"(a[2]), "r"(a[3]), "r"(b[0]), "r"(b[1]));
}
__device__ __forceinline__ void sts128(uint32_t a, uint4 v) {
    asm volatile("st.shared.v4.b32 [%0], {%1,%2,%3,%4};"
                 :: "r"(a), "r"(v.x), "r"(v.y), "r"(v.z), "r"(v.w));
}
__device__ __forceinline__ void splitbf(float v, __nv_bfloat16& h, __nv_bfloat16& l) {
    h = __float2bfloat16(v);
    l = __float2bfloat16(v - __bfloat162float(h));
}

// ---------------- graph structure ----------------
__global__ void hist_kernel(const int* __restrict__ src, const int* __restrict__ tgt) {
    int e = blockIdx.x * blockDim.x + threadIdx.x;
    if (e >= EE) return;
    atomicAdd(&g_cntf[tgt[e]], 1);
    atomicAdd(&g_cntr[src[e]], 1);
}

__global__ void scan_kernel() {
    const int* cnt = blockIdx.x ? g_cntr : g_cntf;
    int* off       = blockIdx.x ? g_offr : g_offf;
    __shared__ int wsum[32];
    __shared__ int chunk_total;
    __shared__ int carry;
    int tid = threadIdx.x, lane = tid & 31, wid = tid >> 5;
    if (tid == 0) carry = 0;
    __syncthreads();
    for (int base = 0; base < NN; base += 1024) {
        int i = base + tid;
        int v = (i < NN) ? cnt[i] : 0;
        int x = v;
        #pragma unroll
        for (int d = 1; d < 32; d <<= 1) {
            int t = __shfl_up_sync(0xffffffffu, x, d);
            if (lane >= d) x += t;
        }
        if (lane == 31) wsum[wid] = x;
        __syncthreads();
        if (wid == 0) {
            int wv = wsum[lane];
            int y = wv;
            #pragma unroll
            for (int d = 1; d < 32; d <<= 1) {
                int t = __shfl_up_sync(0xffffffffu, y, d);
                if (lane >= d) y += t;
            }
            if (lane == 31) chunk_total = y;
            wsum[lane] = y - wv;
        }
        __syncthreads();
        if (i < NN) off[i] = carry + wsum[wid] + (x - v);
        __syncthreads();
        if (tid == 0) carry += chunk_total;
        __syncthreads();
    }
    if (threadIdx.x == 0) off[NN] = carry;
}

__global__ void invcur_kernel() {
    int i = blockIdx.x * blockDim.x + threadIdx.x;
    if (i >= NN) return;
    g_invf[i] = 1.f / fmaxf((float)g_cntf[i], 1.f);
    g_invr[i] = 1.f / fmaxf((float)g_cntr[i], 1.f);
    g_curf[i] = g_offf[i];
    g_curr[i] = g_offr[i];
}

__global__ void fill_kernel(const int* __restrict__ src, const int* __restrict__ tgt) {
    int e = blockIdx.x * blockDim.x + threadIdx.x;
    if (e >= EE) return;
    int s = src[e], t = tgt[e];
    g_csrf[atomicAdd(&g_curf[t], 1)] = s;
    g_csrr[atomicAdd(&g_curr[s], 1)] = t;
}

// ---------------- weight prep: transpose to [n][k], split hi/lo ----------------
__global__ void prep_wpre(const float* __restrict__ preW) {
    int idx = blockIdx.x * blockDim.x + threadIdx.x;
    if (idx >= 256 * KPRE) return;
    int n = idx / KPRE, k = idx % KPRE;
    float v = (k < KIN) ? preW[(size_t)k * 256 + n] : 0.f;
    __nv_bfloat16 h, l;
    splitbf(v, h, l);
    g_wpre[idx] = h;
    g_wpre[256 * KPRE + idx] = l;
}

// n in 0..511: mat = n>>7 (0:convWl 1:convWr 2:revWl 3:revWr), o = n&127
__global__ void prep_wlay(const float* __restrict__ cwl, const float* __restrict__ cwr,
                          const float* __restrict__ rwl, const float* __restrict__ rwr) {
    int idx = blockIdx.x * blockDim.x + threadIdx.x;
    if (idx >= NL * 512 * 256) return;
    int l = idx >> 17;
    int r2 = idx & 131071;
    int n = r2 >> 8, k = r2 & 255;
    int mat = n >> 7, o = n & 127;
    const float* s = (mat == 0) ? cwl : (mat == 1) ? cwr : (mat == 2) ? rwl : rwr;
    float v = s[(size_t)l * 32768 + k * 128 + o];
    __nv_bfloat16 h, lo;
    splitbf(v, h, lo);
    size_t base = (size_t)l * (2 * 512 * 256) + (size_t)n * 256 + k;
    g_wlay[base] = h;
    g_wlay[base + 512 * 256] = lo;
}

// ---------------- input assembly: fp32 [MROWS, 288] ----------------
__global__ void assemble_kernel(const float* __restrict__ xf, const float* __restrict__ dimf,
                                const float* __restrict__ layf, const float* __restrict__ tilef,
                                const float* __restrict__ emb, const int* __restrict__ opc,
                                const int* __restrict__ batch) {
    size_t idx = (size_t)blockIdx.x * blockDim.x + threadIdx.x;
    if (idx >= (size_t)MROWS * KPRE) return;
    int c = (int)(idx % KPRE);
    int rr = (int)(idx / KPRE);
    int n = rr % NN;
    int s = rr / NN;
    float v;
    if (c < 53)       v = xf[(size_t)n * 53 + c];
    else if (c < 85)  v = emb[(size_t)opc[n] * 32 + (c - 53)];
    else if (c < 223) v = dimf[(size_t)n * 138 + (c - 85)];
    else if (c < 247) v = layf[((size_t)n * SAMP + s) * 24 + (c - 223)];
    else if (c < KIN) v = tilef[((size_t)batch[n] * SAMP + s) * 18 + (c - 247)];
    else              v = 0.f;
    g_xin[idx] = v;
}

// ---------------- bf16 split-3 mma GEMM ----------------
// C[M,Ntot] = A[M,K] (fp32) * W[K,Ntot]  (W pre-split bf16, stored [plane][n][k])
// CTA 128x128, 256 threads, 8 warps (4m x 2n), warp tile 32x64.
// SMEM buffer (x2): Ah[128][40] Al[128][40] Bh[128][40] Bl[128][40] bf16 (pad stride 80B).
constexpr int GEMM_SMEM = 2 * 40960;

__device__ __forceinline__ void storeAfrag(uint32_t abase, int r, int kseg, const float4* av) {
    __align__(16) __nv_bfloat16 hi[16], lo[16];
    const float* f = reinterpret_cast<const float*>(av);
    #pragma unroll
    for (int q = 0; q < 16; q++) splitbf(f[q], hi[q], lo[q]);
    uint32_t d = abase + (uint32_t)(r * 80 + kseg * 2);
    const uint4* H = reinterpret_cast<const uint4*>(hi);
    const uint4* L = reinterpret_cast<const uint4*>(lo);
    sts128(d, H[0]);
    sts128(d + 16, H[1]);
    sts128(d + 10240, L[0]);
    sts128(d + 10240 + 16, L[1]);
}

__global__ __launch_bounds__(256, 2) void gemm_mma(
    const float* __restrict__ A, int lda, int kchunks,
    const __nv_bfloat16* __restrict__ W, int kw, int planeStride,
    const float* __restrict__ bias, int dorelu,
    float* __restrict__ C, int ldc) {
    extern __shared__ char smem[];
    uint32_t sb = smem_u32(smem);
    const int tid = threadIdx.x;
    const int lane = tid & 31, wid = tid >> 5;
    const int wm = wid >> 1, wn = wid & 1;
    const size_t m0 = (size_t)blockIdx.x * 128;
    const int n0 = blockIdx.y * 128;

    float acc[2][8][4];
    #pragma unroll
    for (int i = 0; i < 2; i++)
        #pragma unroll
        for (int j = 0; j < 8; j++)
            #pragma unroll
            for (int q = 0; q < 4; q++) acc[i][j][q] = 0.f;

    const int ar = tid >> 1, kseg = (tid & 1) * 16;
    const float* aRow = A + (m0 + ar) * (size_t)lda + kseg;

    float4 av[4];
    // prologue: stage chunk 0 into buf 0
    {
        #pragma unroll
        for (int q = 0; q < 4; q++) {
            int u = tid * 4 + q;
            int plane = u >> 9, rem = u & 511, n = rem >> 2, seg = rem & 3;
            const __nv_bfloat16* s = W + (size_t)plane * planeStride + (size_t)(n0 + n) * kw + seg * 8;
            cp16(sb + 20480 + plane * 10240 + (uint32_t)(n * 80 + seg * 16), s);
        }
        cp_commit();
        #pragma unroll
        for (int q = 0; q < 4; q++) av[q] = *reinterpret_cast<const float4*>(aRow + 4 * q);
        storeAfrag(sb, ar, kseg, av);
        cp_wait0();
    }
    __syncthreads();

    int buf = 0;
    for (int ch = 0; ch < kchunks; ch++) {
        int nxt = ch + 1;
        if (nxt < kchunks) {
            #pragma unroll
            for (int q = 0; q < 4; q++) {
                int u = tid * 4 + q;
                int plane = u >> 9, rem = u & 511, n = rem >> 2, seg = rem & 3;
                const __nv_bfloat16* s = W + (size_t)plane * planeStride + (size_t)(n0 + n) * kw
                                         + nxt * 32 + seg * 8;
                cp16(sb + (buf ^ 1) * 40960 + 20480 + plane * 10240 + (uint32_t)(n * 80 + seg * 16), s);
            }
            cp_commit();
            #pragma unroll
            for (int q = 0; q < 4; q++) av[q] = *reinterpret_cast<const float4*>(aRow + nxt * 32 + 4 * q);
        }
        // ---- MMA on current buffer ----
        {
            uint32_t aB = sb + buf * 40960;
            uint32_t bB = aB + 20480;
            int sub = lane >> 3, rr = lane & 7;
            int ro = (sub & 1) * 8 + rr;
            int co = ((sub >> 1) & 1) * 8;
            #pragma unroll
            for (int kk = 0; kk < 32; kk += 16) {
                uint32_t ah[2][4], axl[2][4], bfr[8][2];
                #pragma unroll
                for (int mi = 0; mi < 2; mi++)
                    ldsm4(ah[mi], aB + (uint32_t)((wm * 32 + mi * 16 + ro) * 80 + (kk + co) * 2));
                #pragma unroll
                for (int j2 = 0; j2 < 4; j2++) {
                    uint32_t t4[4];
                    ldsm4(t4, bB + (uint32_t)((wn * 64 + j2 * 16 + ro) * 80 + (kk + co) * 2));
                    bfr[2 * j2][0] = t4[0]; bfr[2 * j2][1] = t4[2];
                    bfr[2 * j2 + 1][0] = t4[1]; bfr[2 * j2 + 1][1] = t4[3];
                }
                #pragma unroll
                for (int mi = 0; mi < 2; mi++)
                    #pragma unroll
                    for (int nj = 0; nj < 8; nj++) mma16816(acc[mi][nj], ah[mi], bfr[nj]);
                #pragma unroll
                for (int mi = 0; mi < 2; mi++)
                    ldsm4(axl[mi], aB + 10240 + (uint32_t)((wm * 32 + mi * 16 + ro) * 80 + (kk + co) * 2));
                #pragma unroll
                for (int mi = 0; mi < 2; mi++)
                    #pragma unroll
                    for (int nj = 0; nj < 8; nj++) mma16816(acc[mi][nj], axl[mi], bfr[nj]);
                #pragma unroll
                for (int j2 = 0; j2 < 4; j2++) {
                    uint32_t t4[4];
                    ldsm4(t4, bB + 10240 + (uint32_t)((wn * 64 + j2 * 16 + ro) * 80 + (kk + co) * 2));
                    bfr[2 * j2][0] = t4[0]; bfr[2 * j2][1] = t4[2];
                    bfr[2 * j2 + 1][0] = t4[1]; bfr[2 * j2 + 1][1] = t4[3];
                }
                #pragma unroll
                for (int mi = 0; mi < 2; mi++)
                    #pragma unroll
                    for (int nj = 0; nj < 8; nj++) mma16816(acc[mi][nj], ah[mi], bfr[nj]);
            }
        }
        if (nxt < kchunks) {
            storeAfrag(sb + (buf ^ 1) * 40960, ar, kseg, av);
            cp_wait0();
        }
        __syncthreads();
        buf ^= 1;
    }

    // epilogue
    int g = lane >> 2, t4i = lane & 3;
    #pragma unroll
    for (int mi = 0; mi < 2; mi++) {
        #pragma unroll
        for (int nj = 0; nj < 8; nj++) {
            size_t row = m0 + wm * 32 + mi * 16 + g;
            int col = n0 + wn * 64 + nj * 8 + t4i * 2;
            float2 v0 = make_float2(acc[mi][nj][0], acc[mi][nj][1]);
            float2 v1 = make_float2(acc[mi][nj][2], acc[mi][nj][3]);
            if (bias) {
                float b0v = bias[col], b1v = bias[col + 1];
                v0.x += b0v; v0.y += b1v; v1.x += b0v; v1.y += b1v;
            }
            if (dorelu) {
                v0.x = fmaxf(v0.x, 0.f); v0.y = fmaxf(v0.y, 0.f);
                v1.x = fmaxf(v1.x, 0.f); v1.y = fmaxf(v1.y, 0.f);
            }
            *reinterpret_cast<float2*>(C + row * ldc + col) = v0;
            *reinterpret_cast<float2*>(C + (row + 8) * ldc + col) = v1;
        }
    }
}

// ---------------- fused gather + epilogue ----------------
// P cols: [0:128)=X*Wl_f  [128:256)=X*Wr_f  [256:384)=X*Wl_r  [384:512)=X*Wr_r
// Xout[:, :128] = relu(mean_fwd(P_f)+R_f+bconv); Xout[:,128:] = relu(mean_rev(P_r)+R_r+brev)
__device__ __forceinline__ void add4(float4& a, float4 b) {
    a.x += b.x; a.y += b.y; a.z += b.z; a.w += b.w;
}
__global__ void gather_ep(const float* __restrict__ P,
                          const float* __restrict__ bconv, const float* __restrict__ brev,
                          float* __restrict__ X) {
    int w = (blockIdx.x * blockDim.x + threadIdx.x) >> 5;
    int lane = threadIdx.x & 31;
    if (w >= NN) return;
    int c4 = lane * 4;
    float4 aF0 = make_float4(0, 0, 0, 0), aF1 = aF0, aR0 = aF0, aR1 = aF0;
    int b0 = g_offf[w], b1 = g_offf[w + 1];
    for (int j = b0; j < b1; j++) {
        int nb = g_csrf[j];
        add4(aF0, *reinterpret_cast<const float4*>(P + (size_t)nb * 512 + c4));
        add4(aF1, *reinterpret_cast<const float4*>(P + (size_t)(NN + nb) * 512 + c4));
    }
    b0 = g_offr[w]; b1 = g_offr[w + 1];
    for (int j = b0; j < b1; j++) {
        int nb = g_csrr[j];
        add4(aR0, *reinterpret_cast<const float4*>(P + (size_t)nb * 512 + 256 + c4));
        add4(aR1, *reinterpret_cast<const float4*>(P + (size_t)(NN + nb) * 512 + 256 + c4));
    }
    float ivf = g_invf[w], ivr = g_invr[w];
    float4 bc = *reinterpret_cast<const float4*>(bconv + c4);
    float4 br = *reinterpret_cast<const float4*>(brev + c4);
    #pragma unroll
    for (int s = 0; s < SAMP; s++) {
        size_t rowm = (size_t)s * NN + w;
        float4 aF = s ? aF1 : aF0;
        float4 aR = s ? aR1 : aR0;
        float4 rf = *reinterpret_cast<const float4*>(P + rowm * 512 + 128 + c4);
        float4 rr = *reinterpret_cast<const float4*>(P + rowm * 512 + 384 + c4);
        float4 oF, oR;
        oF.x = fmaxf(aF.x * ivf + rf.x + bc.x, 0.f);
        oF.y = fmaxf(aF.y * ivf + rf.y + bc.y, 0.f);
        oF.z = fmaxf(aF.z * ivf + rf.z + bc.z, 0.f);
        oF.w = fmaxf(aF.w * ivf + rf.w + bc.w, 0.f);
        oR.x = fmaxf(aR.x * ivr + rr.x + br.x, 0.f);
        oR.y = fmaxf(aR.y * ivr + rr.y + br.y, 0.f);
        oR.z = fmaxf(aR.z * ivr + rr.z + br.z, 0.f);
        oR.w = fmaxf(aR.w * ivr + rr.w + br.w, 0.f);
        *reinterpret_cast<float4*>(X + rowm * MIDC + c4) = oF;
        *reinterpret_cast<float4*>(X + rowm * MIDC + 128 + c4) = oR;
    }
}

// ---------------- head ----------------
__global__ void init_out_kernel(float* out, const float* __restrict__ hb) {
    int i = threadIdx.x;
    if (i < GG * SAMP) out[i] = hb[0];
}

__global__ void head_kernel(const float* __restrict__ x2, const float* __restrict__ x3,
                            const float* __restrict__ hw, const int* __restrict__ batch,
                            float* __restrict__ out) {
    __shared__ float part[GG * SAMP];
    int tid = threadIdx.x;
    if (tid < GG * SAMP) part[tid] = 0.f;
    __syncthreads();
    int w = (blockIdx.x * blockDim.x + tid) >> 5;
    int lane = tid & 31;
    if (w < NN) {
        int g = batch[w];
        #pragma unroll
        for (int s = 0; s < SAMP; s++) {
            const float* p2 = x2 + ((size_t)s * NN + w) * MIDC;
            const float* p3 = x3 + ((size_t)s * NN + w) * MIDC;
            float sum = 0.f;
            #pragma unroll
            for (int c = lane; c < MIDC; c += 32)
                sum += p2[c] * hw[c] + p3[c] * hw[MIDC + c];
            #pragma unroll
            for (int d = 16; d > 0; d >>= 1) sum += __shfl_down_sync(0xffffffffu, sum, d);
            if (lane == 0) atomicAdd(&part[g * SAMP + s], sum);
        }
    }
    __syncthreads();
    if (tid < GG * SAMP && part[tid] != 0.f) atomicAdd(&out[tid], part[tid]);
}

// ---------------- launch ----------------
extern "C" void kernel_launch(void* const* d_in, const int* in_sizes, int n_in,
                              void* d_out, int out_size) {
    const float* x_feat    = (const float*)d_in[0];
    const float* dim_feat  = (const float*)d_in[1];
    const float* lay_feat  = (const float*)d_in[2];
    const float* tile_feat = (const float*)d_in[3];
    const float* emb       = (const float*)d_in[4];
    const float* preW      = (const float*)d_in[5];
    const float* preb      = (const float*)d_in[6];
    const float* convWl    = (const float*)d_in[7];
    const float* convWr    = (const float*)d_in[8];
    const float* convb     = (const float*)d_in[9];
    const float* revWl     = (const float*)d_in[10];
    const float* revWr     = (const float*)d_in[11];
    const float* revb      = (const float*)d_in[12];
    const float* headW     = (const float*)d_in[13];
    const float* headb     = (const float*)d_in[14];
    const int*   opcode    = (const int*)d_in[15];
    const int*   batch     = (const int*)d_in[16];
    const int*   eidx      = (const int*)d_in[17];
    const int* src = eidx;
    const int* tgt = eidx + EE;
    float* out = (float*)d_out;

    int *cntf, *cntr;
    float *xin, *xa, *xb, *P;
    __nv_bfloat16 *wpre, *wlay;
    cudaGetSymbolAddress((void**)&cntf, g_cntf);
    cudaGetSymbolAddress((void**)&cntr, g_cntr);
    cudaGetSymbolAddress((void**)&xin, g_xin);
    cudaGetSymbolAddress((void**)&xa, g_xa);
    cudaGetSymbolAddress((void**)&xb, g_xb);
    cudaGetSymbolAddress((void**)&P, g_P);
    cudaGetSymbolAddress((void**)&wpre, g_wpre);
    cudaGetSymbolAddress((void**)&wlay, g_wlay);

    static bool attr_done = false;
    if (!attr_done) {
        cudaFuncSetAttribute(gemm_mma, cudaFuncAttributeMaxDynamicSharedMemorySize, GEMM_SMEM);
        attr_done = true;
    }

    // graph structure
    cudaMemsetAsync(cntf, 0, NN * sizeof(int), 0);
    cudaMemsetAsync(cntr, 0, NN * sizeof(int), 0);
    hist_kernel<<<(EE + 255) / 256, 256>>>(src, tgt);
    scan_kernel<<<2, 1024>>>();
    invcur_kernel<<<(NN + 255) / 256, 256>>>();
    fill_kernel<<<(EE + 255) / 256, 256>>>(src, tgt);

    // weights + input
    prep_wpre<<<(256 * KPRE + 255) / 256, 256>>>(preW);
    prep_wlay<<<(NL * 512 * 256 + 255) / 256, 256>>>(convWl, convWr, revWl, revWr);
    {
        size_t total = (size_t)MROWS * KPRE;
        assemble_kernel<<<(unsigned)((total + 255) / 256), 256>>>(
            x_feat, dim_feat, lay_feat, tile_feat, emb, opcode, batch);
    }

    // pre GEMM: xa = relu(xin @ preW + preb)   [K=288 (9 chunks), N=256]
    {
        dim3 grid(MTILES, 2);
        gemm_mma<<<grid, 256, GEMM_SMEM>>>(xin, KPRE, KPRE / 32, wpre, KPRE, 256 * KPRE,
                                           preb, 1, xa, 256);
    }

    float *cur = xa, *nxt = xb;
    for (int i = 0; i < NL; i++) {
        dim3 grid(MTILES, 4);
        gemm_mma<<<grid, 256, GEMM_SMEM>>>(cur, 256, 8,
                                           wlay + (size_t)i * (2 * 512 * 256), 256, 512 * 256,
                                           nullptr, 0, P, 512);
        gather_ep<<<(NN * 32 + 255) / 256, 256>>>(P, convb + i * 128, revb + i * 128, nxt);
        float* t = cur; cur = nxt; nxt = t;
    }
    // layer outputs: i=2 -> xb, i=3 -> xa

    init_out_kernel<<<1, 32>>>(out, headb);
    head_kernel<<<(NN * 32 + 255) / 256, 256>>>(xb, xa, headW, batch, out);
}

// round 6
// speedup vs baseline: 1.9463x; 1.0472x over previous
#include <cuda_runtime.h>
#include <cuda_bf16.h>
#include <cstdint>

// ---------------- problem constants ----------------
constexpr int NN   = 100000;
constexpr int SAMP = 2;
constexpr int GG   = 8;
constexpr int EE   = 400000;
constexpr int MIDC = 256;
constexpr int NL   = 4;
constexpr int KIN  = 265;
constexpr int KPRE = 288;              // padded input K (9 chunks of 32)
constexpr int MROWS = SAMP * NN;       // 200000
constexpr int MPAD  = 200064;          // 1563 * 128
constexpr int MTILES = MPAD / 128;

// ---------------- static scratch (all activations = dual bf16 planes) ----------------
__device__ __nv_bfloat16 g_xin_h[(size_t)MPAD * KPRE];
__device__ __nv_bfloat16 g_xin_l[(size_t)MPAD * KPRE];
__device__ __nv_bfloat16 g_xa_h[(size_t)MPAD * MIDC];
__device__ __nv_bfloat16 g_xa_l[(size_t)MPAD * MIDC];
__device__ __nv_bfloat16 g_xb_h[(size_t)MPAD * MIDC];
__device__ __nv_bfloat16 g_xb_l[(size_t)MPAD * MIDC];
__device__ float g_P[(size_t)MPAD * 512];
__device__ __nv_bfloat16 g_wpre[2 * 256 * KPRE];        // [plane][n256][k288]
__device__ __nv_bfloat16 g_wlay[NL * 2 * 512 * 256];    // [l][plane][n512][k256]
__device__ int   g_cntf[NN], g_cntr[NN];
__device__ int   g_offf[NN + 1], g_offr[NN + 1];
__device__ int   g_curf[NN], g_curr[NN];
__device__ int   g_csrf[EE], g_csrr[EE];
__device__ float g_invf[NN], g_invr[NN];

// ---------------- PTX helpers ----------------
__device__ __forceinline__ uint32_t smem_u32(const void* p) {
    uint32_t a;
    asm("{ .reg .u64 t; cvta.to.shared.u64 t, %1; cvt.u32.u64 %0, t; }" : "=r"(a) : "l"(p));
    return a;
}
__device__ __forceinline__ void cp16(uint32_t dst, const void* src) {
    asm volatile("cp.async.ca.shared.global [%0], [%1], 16;" :: "r"(dst), "l"(src));
}
__device__ __forceinline__ void cp_commit() { asm volatile("cp.async.commit_group;"); }
__device__ __forceinline__ void cp_wait0()  { asm volatile("cp.async.wait_group 0;"); }
__device__ __forceinline__ void ldsm4(uint32_t* r, uint32_t a) {
    asm volatile("ldmatrix.sync.aligned.m8n8.x4.shared.b16 {%0,%1,%2,%3}, [%4];"
                 : "=r"(r[0]), "=r"(r[1]), "=r"(r[2]), "=r"(r[3]) : "r"(a));
}
__device__ __forceinline__ void mma16816(float* d, const uint32_t* a, const uint32_t* b) {
    asm volatile("mma.sync.aligned.m16n8k16.row.col.f32.bf16.bf16.f32 "
                 "{%0,%1,%2,%3}, {%4,%5,%6,%7}, {%8,%9}, {%0,%1,%2,%3};"
                 : "+f"(d[0]), "+f"(d[1]), "+f"(d[2]), "+f"(d[3])
                 : "r"(a[0]), "r"(a[1]), "r"(a[2]), "r"(a[3]), "r"(b[0]), "r"(b[1]));
}
__device__ __forceinline__ void splitbf(float v, __nv_bfloat16& h, __nv_bfloat16& l) {
    h = __float2bfloat16(v);
    l = __float2bfloat16(v - __bfloat162float(h));
}

// ---------------- graph structure ----------------
__global__ void hist_kernel(const int* __restrict__ src, const int* __restrict__ tgt) {
    int e = blockIdx.x * blockDim.x + threadIdx.x;
    if (e >= EE) return;
    atomicAdd(&g_cntf[tgt[e]], 1);
    atomicAdd(&g_cntr[src[e]], 1);
}

__global__ void scan_kernel() {
    const int* cnt = blockIdx.x ? g_cntr : g_cntf;
    int* off       = blockIdx.x ? g_offr : g_offf;
    __shared__ int wsum[32];
    __shared__ int chunk_total;
    __shared__ int carry;
    int tid = threadIdx.x, lane = tid & 31, wid = tid >> 5;
    if (tid == 0) carry = 0;
    __syncthreads();
    for (int base = 0; base < NN; base += 1024) {
        int i = base + tid;
        int v = (i < NN) ? cnt[i] : 0;
        int x = v;
        #pragma unroll
        for (int d = 1; d < 32; d <<= 1) {
            int t = __shfl_up_sync(0xffffffffu, x, d);
            if (lane >= d) x += t;
        }
        if (lane == 31) wsum[wid] = x;
        __syncthreads();
        if (wid == 0) {
            int wv = wsum[lane];
            int y = wv;
            #pragma unroll
            for (int d = 1; d < 32; d <<= 1) {
                int t = __shfl_up_sync(0xffffffffu, y, d);
                if (lane >= d) y += t;
            }
            if (lane == 31) chunk_total = y;
            wsum[lane] = y - wv;
        }
        __syncthreads();
        if (i < NN) off[i] = carry + wsum[wid] + (x - v);
        __syncthreads();
        if (tid == 0) carry += chunk_total;
        __syncthreads();
    }
    if (threadIdx.x == 0) off[NN] = carry;
}

__global__ void invcur_kernel() {
    int i = blockIdx.x * blockDim.x + threadIdx.x;
    if (i >= NN) return;
    g_invf[i] = 1.f / fmaxf((float)g_cntf[i], 1.f);
    g_invr[i] = 1.f / fmaxf((float)g_cntr[i], 1.f);
    g_curf[i] = g_offf[i];
    g_curr[i] = g_offr[i];
}

__global__ void fill_kernel(const int* __restrict__ src, const int* __restrict__ tgt) {
    int e = blockIdx.x * blockDim.x + threadIdx.x;
    if (e >= EE) return;
    int s = src[e], t = tgt[e];
    g_csrf[atomicAdd(&g_curf[t], 1)] = s;
    g_csrr[atomicAdd(&g_curr[s], 1)] = t;
}

// ---------------- weight prep ----------------
__global__ void prep_wpre(const float* __restrict__ preW) {
    int idx = blockIdx.x * blockDim.x + threadIdx.x;
    if (idx >= 256 * KPRE) return;
    int n = idx / KPRE, k = idx % KPRE;
    float v = (k < KIN) ? preW[(size_t)k * 256 + n] : 0.f;
    __nv_bfloat16 h, l;
    splitbf(v, h, l);
    g_wpre[idx] = h;
    g_wpre[256 * KPRE + idx] = l;
}

__global__ void prep_wlay(const float* __restrict__ cwl, const float* __restrict__ cwr,
                          const float* __restrict__ rwl, const float* __restrict__ rwr) {
    int idx = blockIdx.x * blockDim.x + threadIdx.x;
    if (idx >= NL * 512 * 256) return;
    int l = idx >> 17;
    int r2 = idx & 131071;
    int n = r2 >> 8, k = r2 & 255;
    int mat = n >> 7, o = n & 127;
    const float* s = (mat == 0) ? cwl : (mat == 1) ? cwr : (mat == 2) ? rwl : rwr;
    float v = s[(size_t)l * 32768 + k * 128 + o];
    __nv_bfloat16 h, lo;
    splitbf(v, h, lo);
    size_t base = (size_t)l * (2 * 512 * 256) + (size_t)n * 256 + k;
    g_wlay[base] = h;
    g_wlay[base + 512 * 256] = lo;
}

// ---------------- input assembly -> bf16 planes ----------------
__global__ void assemble_kernel(const float* __restrict__ xf, const float* __restrict__ dimf,
                                const float* __restrict__ layf, const float* __restrict__ tilef,
                                const float* __restrict__ emb, const int* __restrict__ opc,
                                const int* __restrict__ batch) {
    size_t idx = (size_t)blockIdx.x * blockDim.x + threadIdx.x;
    if (idx >= (size_t)MROWS * KPRE) return;
    int c = (int)(idx % KPRE);
    int rr = (int)(idx / KPRE);
    int n = rr % NN;
    int s = rr / NN;
    float v;
    if (c < 53)       v = xf[(size_t)n * 53 + c];
    else if (c < 85)  v = emb[(size_t)opc[n] * 32 + (c - 53)];
    else if (c < 223) v = dimf[(size_t)n * 138 + (c - 85)];
    else if (c < 247) v = layf[((size_t)n * SAMP + s) * 24 + (c - 223)];
    else if (c < KIN) v = tilef[((size_t)batch[n] * SAMP + s) * 18 + (c - 247)];
    else              v = 0.f;
    __nv_bfloat16 h, l;
    splitbf(v, h, l);
    g_xin_h[idx] = h;
    g_xin_l[idx] = l;
}

// ---------------- bf16 split-3 mma GEMM (A pre-split in global) ----------------
// CTA 128x256, 512 threads, 16 warps (4m x 4n), warp 32x64.
// Stage: Ah[128][40] Al[128][40] (10240 ea) + Bh[256][40] Bl[256][40] (20480 ea) = 61440 B.
constexpr int STAGE = 61440;
constexpr int GEMM_SMEM = 2 * STAGE;

__global__ __launch_bounds__(512, 1) void gemm_mma(
    const __nv_bfloat16* __restrict__ Ah, const __nv_bfloat16* __restrict__ Al,
    int lda, int kchunks,
    const __nv_bfloat16* __restrict__ W, int kw, size_t planeStride,
    const float* __restrict__ bias, int mode,   // 0: fp32 C; 1: bias+relu -> planes
    float* __restrict__ Cf, __nv_bfloat16* __restrict__ Oh, __nv_bfloat16* __restrict__ Ol,
    int ldc) {
    extern __shared__ char smem[];
    uint32_t sb = smem_u32(smem);
    const int tid = threadIdx.x;
    const int lane = tid & 31, wid = tid >> 5;
    const int wm = wid >> 2, wn = wid & 3;
    const size_t m0 = (size_t)blockIdx.x * 128;
    const int n0 = blockIdx.y * 256;

    // per-thread cp.async descriptors (6 chunks of 16B per stage)
    const __nv_bfloat16* srcb[6];
    uint32_t dsto[6];
    #pragma unroll
    for (int i = 0; i < 6; i++) {
        int u = tid + i * 512;
        if (i < 2) {
            int plane = u >> 9, rem = u & 511, row = rem >> 2, seg = rem & 3;
            srcb[i] = (plane ? Al : Ah) + (m0 + row) * (size_t)lda + seg * 8;
            dsto[i] = (uint32_t)(plane * 10240 + row * 80 + seg * 16);
        } else {
            int v = u - 1024;
            int plane = v >> 10, rem = v & 1023, n = rem >> 2, seg = rem & 3;
            srcb[i] = W + (size_t)plane * planeStride + (size_t)(n0 + n) * kw + seg * 8;
            dsto[i] = (uint32_t)(20480 + plane * 20480 + n * 80 + seg * 16);
        }
    }

    float acc[2][8][4];
    #pragma unroll
    for (int i = 0; i < 2; i++)
        #pragma unroll
        for (int j = 0; j < 8; j++)
            #pragma unroll
            for (int q = 0; q < 4; q++) acc[i][j][q] = 0.f;

    // prologue: stage 0
    #pragma unroll
    for (int i = 0; i < 6; i++) cp16(sb + dsto[i], srcb[i]);
    cp_commit();
    cp_wait0();
    __syncthreads();

    const int sub = lane >> 3, rr = lane & 7;
    const int ro = (sub & 1) * 8 + rr;
    const int co = ((sub >> 1) & 1) * 8;

    int buf = 0;
    for (int ch = 0; ch < kchunks; ch++) {
        int nxt = ch + 1;
        if (nxt < kchunks) {
            uint32_t db = sb + (buf ^ 1) * STAGE;
            int koff = nxt * 32;
            #pragma unroll
            for (int i = 0; i < 6; i++) cp16(db + dsto[i], srcb[i] + koff);
            cp_commit();
        }
        uint32_t base = sb + buf * STAGE;
        #pragma unroll
        for (int kk = 0; kk < 32; kk += 16) {
            uint32_t ah[2][4], al[2][4];
            #pragma unroll
            for (int mi = 0; mi < 2; mi++) {
                uint32_t rowoff = (uint32_t)((wm * 32 + mi * 16 + ro) * 80 + (kk + co) * 2);
                ldsm4(ah[mi], base + rowoff);
                ldsm4(al[mi], base + 10240 + rowoff);
            }
            #pragma unroll
            for (int hn = 0; hn < 2; hn++) {
                uint32_t bfr[4][2];
                #pragma unroll
                for (int j2 = 0; j2 < 2; j2++) {
                    uint32_t t4[4];
                    ldsm4(t4, base + 20480 +
                          (uint32_t)((wn * 64 + hn * 32 + j2 * 16 + ro) * 80 + (kk + co) * 2));
                    bfr[2 * j2][0] = t4[0]; bfr[2 * j2][1] = t4[2];
                    bfr[2 * j2 + 1][0] = t4[1]; bfr[2 * j2 + 1][1] = t4[3];
                }
                #pragma unroll
                for (int mi = 0; mi < 2; mi++)
                    #pragma unroll
                    for (int nj = 0; nj < 4; nj++)
                        mma16816(acc[mi][hn * 4 + nj], ah[mi], bfr[nj]);
                #pragma unroll
                for (int mi = 0; mi < 2; mi++)
                    #pragma unroll
                    for (int nj = 0; nj < 4; nj++)
                        mma16816(acc[mi][hn * 4 + nj], al[mi], bfr[nj]);
                #pragma unroll
                for (int j2 = 0; j2 < 2; j2++) {
                    uint32_t t4[4];
                    ldsm4(t4, base + 40960 +
                          (uint32_t)((wn * 64 + hn * 32 + j2 * 16 + ro) * 80 + (kk + co) * 2));
                    bfr[2 * j2][0] = t4[0]; bfr[2 * j2][1] = t4[2];
                    bfr[2 * j2 + 1][0] = t4[1]; bfr[2 * j2 + 1][1] = t4[3];
                }
                #pragma unroll
                for (int mi = 0; mi < 2; mi++)
                    #pragma unroll
                    for (int nj = 0; nj < 4; nj++)
                        mma16816(acc[mi][hn * 4 + nj], ah[mi], bfr[nj]);
            }
        }
        if (nxt < kchunks) cp_wait0();
        __syncthreads();
        buf ^= 1;
    }

    // epilogue
    const int g = lane >> 2, t4i = lane & 3;
    #pragma unroll
    for (int mi = 0; mi < 2; mi++) {
        #pragma unroll
        for (int nj = 0; nj < 8; nj++) {
            size_t row = m0 + wm * 32 + mi * 16 + g;
            int col = n0 + wn * 64 + nj * 8 + t4i * 2;
            float2 v0 = make_float2(acc[mi][nj][0], acc[mi][nj][1]);
            float2 v1 = make_float2(acc[mi][nj][2], acc[mi][nj][3]);
            if (mode == 0) {
                *reinterpret_cast<float2*>(Cf + row * ldc + col) = v0;
                *reinterpret_cast<float2*>(Cf + (row + 8) * ldc + col) = v1;
            } else {
                float b0v = bias[col], b1v = bias[col + 1];
                v0.x = fmaxf(v0.x + b0v, 0.f); v0.y = fmaxf(v0.y + b1v, 0.f);
                v1.x = fmaxf(v1.x + b0v, 0.f); v1.y = fmaxf(v1.y + b1v, 0.f);
                __nv_bfloat16 hx, lx, hy, ly;
                splitbf(v0.x, hx, lx); splitbf(v0.y, hy, ly);
                *reinterpret_cast<__nv_bfloat162*>(Oh + row * ldc + col) = __nv_bfloat162(hx, hy);
                *reinterpret_cast<__nv_bfloat162*>(Ol + row * ldc + col) = __nv_bfloat162(lx, ly);
                splitbf(v1.x, hx, lx); splitbf(v1.y, hy, ly);
                *reinterpret_cast<__nv_bfloat162*>(Oh + (row + 8) * ldc + col) = __nv_bfloat162(hx, hy);
                *reinterpret_cast<__nv_bfloat162*>(Ol + (row + 8) * ldc + col) = __nv_bfloat162(lx, ly);
            }
        }
    }
}

// ---------------- fused gather + epilogue -> bf16 planes ----------------
__device__ __forceinline__ void add4(float4& a, float4 b) {
    a.x += b.x; a.y += b.y; a.z += b.z; a.w += b.w;
}
__device__ __forceinline__ void store4_planes(__nv_bfloat16* H, __nv_bfloat16* L,
                                              size_t off, float4 v) {
    __nv_bfloat16 h0, l0, h1, l1, h2, l2, h3, l3;
    splitbf(v.x, h0, l0); splitbf(v.y, h1, l1);
    splitbf(v.z, h2, l2); splitbf(v.w, h3, l3);
    __nv_bfloat162 hp0(h0, h1), hp1(h2, h3), lp0(l0, l1), lp1(l2, l3);
    uint2 hu, lu;
    hu.x = *reinterpret_cast<uint32_t*>(&hp0); hu.y = *reinterpret_cast<uint32_t*>(&hp1);
    lu.x = *reinterpret_cast<uint32_t*>(&lp0); lu.y = *reinterpret_cast<uint32_t*>(&lp1);
    *reinterpret_cast<uint2*>(H + off) = hu;
    *reinterpret_cast<uint2*>(L + off) = lu;
}

__global__ void gather_ep(const float* __restrict__ P,
                          const float* __restrict__ bconv, const float* __restrict__ brev,
                          __nv_bfloat16* __restrict__ Xh, __nv_bfloat16* __restrict__ Xl) {
    int w = (blockIdx.x * blockDim.x + threadIdx.x) >> 5;
    int lane = threadIdx.x & 31;
    if (w >= NN) return;
    int c4 = lane * 4;
    float4 aF0 = make_float4(0, 0, 0, 0), aF1 = aF0, aR0 = aF0, aR1 = aF0;
    int b0 = g_offf[w], b1 = g_offf[w + 1];
    for (int j = b0; j < b1; j++) {
        int nb = g_csrf[j];
        add4(aF0, *reinterpret_cast<const float4*>(P + (size_t)nb * 512 + c4));
        add4(aF1, *reinterpret_cast<const float4*>(P + (size_t)(NN + nb) * 512 + c4));
    }
    b0 = g_offr[w]; b1 = g_offr[w + 1];
    for (int j = b0; j < b1; j++) {
        int nb = g_csrr[j];
        add4(aR0, *reinterpret_cast<const float4*>(P + (size_t)nb * 512 + 256 + c4));
        add4(aR1, *reinterpret_cast<const float4*>(P + (size_t)(NN + nb) * 512 + 256 + c4));
    }
    float ivf = g_invf[w], ivr = g_invr[w];
    float4 bc = *reinterpret_cast<const float4*>(bconv + c4);
    float4 br = *reinterpret_cast<const float4*>(brev + c4);
    #pragma unroll
    for (int s = 0; s < SAMP; s++) {
        size_t rowm = (size_t)s * NN + w;
        float4 aF = s ? aF1 : aF0;
        float4 aR = s ? aR1 : aR0;
        float4 rf = *reinterpret_cast<const float4*>(P + rowm * 512 + 128 + c4);
        float4 rr = *reinterpret_cast<const float4*>(P + rowm * 512 + 384 + c4);
        float4 oF, oR;
        oF.x = fmaxf(aF.x * ivf + rf.x + bc.x, 0.f);
        oF.y = fmaxf(aF.y * ivf + rf.y + bc.y, 0.f);
        oF.z = fmaxf(aF.z * ivf + rf.z + bc.z, 0.f);
        oF.w = fmaxf(aF.w * ivf + rf.w + bc.w, 0.f);
        oR.x = fmaxf(aR.x * ivr + rr.x + br.x, 0.f);
        oR.y = fmaxf(aR.y * ivr + rr.y + br.y, 0.f);
        oR.z = fmaxf(aR.z * ivr + rr.z + br.z, 0.f);
        oR.w = fmaxf(aR.w * ivr + rr.w + br.w, 0.f);
        store4_planes(Xh, Xl, rowm * MIDC + c4, oF);
        store4_planes(Xh, Xl, rowm * MIDC + 128 + c4, oR);
    }
}

// ---------------- head ----------------
__global__ void init_out_kernel(float* out, const float* __restrict__ hb) {
    int i = threadIdx.x;
    if (i < GG * SAMP) out[i] = hb[0];
}

__device__ __forceinline__ void unpack8(float* f, uint4 h, uint4 l) {
    const unsigned* hu = (const unsigned*)&h;
    const unsigned* lu = (const unsigned*)&l;
    #pragma unroll
    for (int q = 0; q < 4; q++) {
        float2 fh = __bfloat1622float2(*(const __nv_bfloat162*)&hu[q]);
        float2 fl = __bfloat1622float2(*(const __nv_bfloat162*)&lu[q]);
        f[2 * q]     = fh.x + fl.x;
        f[2 * q + 1] = fh.y + fl.y;
    }
}

__global__ void head_kernel(const __nv_bfloat16* __restrict__ x2h, const __nv_bfloat16* __restrict__ x2l,
                            const __nv_bfloat16* __restrict__ x3h, const __nv_bfloat16* __restrict__ x3l,
                            const float* __restrict__ hw, const int* __restrict__ batch,
                            float* __restrict__ out) {
    __shared__ float part[GG * SAMP];
    int tid = threadIdx.x;
    if (tid < GG * SAMP) part[tid] = 0.f;
    __syncthreads();
    int w = (blockIdx.x * blockDim.x + tid) >> 5;
    int lane = tid & 31;
    if (w < NN) {
        int g = batch[w];
        float wa[8], wb2[8];
        #pragma unroll
        for (int q = 0; q < 8; q++) {
            wa[q]  = hw[lane * 8 + q];
            wb2[q] = hw[256 + lane * 8 + q];
        }
        #pragma unroll
        for (int s = 0; s < SAMP; s++) {
            size_t r = ((size_t)s * NN + w) * MIDC + lane * 8;
            float f2[8], f3[8];
            unpack8(f2, *(const uint4*)(x2h + r), *(const uint4*)(x2l + r));
            unpack8(f3, *(const uint4*)(x3h + r), *(const uint4*)(x3l + r));
            float sum = 0.f;
            #pragma unroll
            for (int q = 0; q < 8; q++) sum += f2[q] * wa[q] + f3[q] * wb2[q];
            #pragma unroll
            for (int d = 16; d > 0; d >>= 1) sum += __shfl_down_sync(0xffffffffu, sum, d);
            if (lane == 0) atomicAdd(&part[g * SAMP + s], sum);
        }
    }
    __syncthreads();
    if (tid < GG * SAMP && part[tid] != 0.f) atomicAdd(&out[tid], part[tid]);
}

// ---------------- launch ----------------
extern "C" void kernel_launch(void* const* d_in, const int* in_sizes, int n_in,
                              void* d_out, int out_size) {
    const float* x_feat    = (const float*)d_in[0];
    const float* dim_feat  = (const float*)d_in[1];
    const float* lay_feat  = (const float*)d_in[2];
    const float* tile_feat = (const float*)d_in[3];
    const float* emb       = (const float*)d_in[4];
    const float* preW      = (const float*)d_in[5];
    const float* preb      = (const float*)d_in[6];
    const float* convWl    = (const float*)d_in[7];
    const float* convWr    = (const float*)d_in[8];
    const float* convb     = (const float*)d_in[9];
    const float* revWl     = (const float*)d_in[10];
    const float* revWr     = (const float*)d_in[11];
    const float* revb      = (const float*)d_in[12];
    const float* headW     = (const float*)d_in[13];
    const float* headb     = (const float*)d_in[14];
    const int*   opcode    = (const int*)d_in[15];
    const int*   batch     = (const int*)d_in[16];
    const int*   eidx      = (const int*)d_in[17];
    const int* src = eidx;
    const int* tgt = eidx + EE;
    float* out = (float*)d_out;

    int *cntf, *cntr;
    float *P;
    __nv_bfloat16 *xinh, *xinl, *xah, *xal, *xbh, *xbl, *wpre, *wlay;
    cudaGetSymbolAddress((void**)&cntf, g_cntf);
    cudaGetSymbolAddress((void**)&cntr, g_cntr);
    cudaGetSymbolAddress((void**)&xinh, g_xin_h);
    cudaGetSymbolAddress((void**)&xinl, g_xin_l);
    cudaGetSymbolAddress((void**)&xah, g_xa_h);
    cudaGetSymbolAddress((void**)&xal, g_xa_l);
    cudaGetSymbolAddress((void**)&xbh, g_xb_h);
    cudaGetSymbolAddress((void**)&xbl, g_xb_l);
    cudaGetSymbolAddress((void**)&P, g_P);
    cudaGetSymbolAddress((void**)&wpre, g_wpre);
    cudaGetSymbolAddress((void**)&wlay, g_wlay);

    static bool attr_done = false;
    if (!attr_done) {
        cudaFuncSetAttribute(gemm_mma, cudaFuncAttributeMaxDynamicSharedMemorySize, GEMM_SMEM);
        attr_done = true;
    }

    // graph structure
    cudaMemsetAsync(cntf, 0, NN * sizeof(int), 0);
    cudaMemsetAsync(cntr, 0, NN * sizeof(int), 0);
    hist_kernel<<<(EE + 255) / 256, 256>>>(src, tgt);
    scan_kernel<<<2, 1024>>>();
    invcur_kernel<<<(NN + 255) / 256, 256>>>();
    fill_kernel<<<(EE + 255) / 256, 256>>>(src, tgt);

    // weights + input
    prep_wpre<<<(256 * KPRE + 255) / 256, 256>>>(preW);
    prep_wlay<<<(NL * 512 * 256 + 255) / 256, 256>>>(convWl, convWr, revWl, revWr);
    {
        size_t total = (size_t)MROWS * KPRE;
        assemble_kernel<<<(unsigned)((total + 255) / 256), 256>>>(
            x_feat, dim_feat, lay_feat, tile_feat, emb, opcode, batch);
    }

    // pre GEMM: xa_planes = relu(xin @ preW + preb)   [K=288, N=256, one N-tile]
    {
        dim3 grid(MTILES, 1);
        gemm_mma<<<grid, 512, GEMM_SMEM>>>(xinh, xinl, KPRE, KPRE / 32,
                                           wpre, KPRE, (size_t)256 * KPRE,
                                           preb, 1, nullptr, xah, xal, 256);
    }

    __nv_bfloat16 *curh = xah, *curl = xal, *nxth = xbh, *nxtl = xbl;
    for (int i = 0; i < NL; i++) {
        dim3 grid(MTILES, 2);
        gemm_mma<<<grid, 512, GEMM_SMEM>>>(curh, curl, 256, 8,
                                           wlay + (size_t)i * (2 * 512 * 256), 256,
                                           (size_t)512 * 256,
                                           nullptr, 0, P, nullptr, nullptr, 512);
        gather_ep<<<(NN * 32 + 255) / 256, 256>>>(P, convb + i * 128, revb + i * 128,
                                                  nxth, nxtl);
        __nv_bfloat16* t;
        t = curh; curh = nxth; nxth = t;
        t = curl; curl = nxtl; nxtl = t;
    }
    // layer outputs: i=2 -> xb planes, i=3 -> xa planes

    init_out_kernel<<<1, 32>>>(out, headb);
    head_kernel<<<(NN * 32 + 255) / 256, 256>>>(xbh, xbl, xah, xal, headW, batch, out);
}